// round 11
// baseline (speedup 1.0000x reference)
#include <cuda_runtime.h>
#include <cstdint>

#define CIN   80
#define COUT  32
#define BATCH 8
#define HH    160
#define WW    320
#define DD    48
#define HW    (HH*WW)        // 51200
#define WH    160            // half-row width
#define RW    208            // RA row floats (48 halo + 160)
#define SROW  368            // staging row floats: 160 L + 208 R
#define CHUNK 16
#define NCHUNK 5
#define BUFBYTES (CHUNK*SROW*4)   // 23552 B per stage buffer
#define BUFFLT   (CHUNK*SROW)     // 5888 floats

#define OFF_SW   0
#define OFF_SB   20480
#define OFF_MBAR 20736
#define OFF_FEAT 20800
// feat region: staging 2*23552 = 47104 ; final Ls 32*160*4 + RA 32*208*4 = 47104
#define SMEM_TOTAL (20800 + 47104)   // 67904 -> 3 CTAs/SM

typedef unsigned long long ull;

__device__ __forceinline__ ull fma2(ull a, ull b, ull c) {
    ull d;
    asm("fma.rn.f32x2 %0, %1, %2, %3;" : "=l"(d) : "l"(a), "l"(b), "l"(c));
    return d;
}
__device__ __forceinline__ ull mul2(ull a, ull b) {
    ull d;
    asm("mul.rn.f32x2 %0, %1, %2;" : "=l"(d) : "l"(a), "l"(b));
    return d;
}
__device__ __forceinline__ ull pack2(float lo, float hi) {
    ull d;
    asm("mov.b64 %0, {%1, %2};" : "=l"(d) : "f"(lo), "f"(hi));
    return d;
}
__device__ __forceinline__ uint32_t s2u(const void* p) {
    uint32_t a;
    asm("{ .reg .u64 t; cvta.to.shared.u64 t, %1; cvt.u32.u64 %0, t; }" : "=r"(a) : "l"(p));
    return a;
}
__device__ __forceinline__ void bulk1d(uint32_t dst, const void* src, uint32_t bytes, uint32_t mbar) {
    asm volatile("cp.async.bulk.shared::cluster.global.mbarrier::complete_tx::bytes [%0], [%1], %2, [%3];"
                 :: "r"(dst), "l"(src), "r"(bytes), "r"(mbar) : "memory");
}
__device__ __forceinline__ void mbar_init(uint32_t mbar, uint32_t cnt) {
    asm volatile("mbarrier.init.shared.b64 [%0], %1;" :: "r"(mbar), "r"(cnt) : "memory");
}
__device__ __forceinline__ void mbar_expect(uint32_t mbar, uint32_t tx) {
    asm volatile("mbarrier.arrive.expect_tx.shared.b64 _, [%0], %1;" :: "r"(mbar), "r"(tx) : "memory");
}
__device__ __forceinline__ void mbar_wait(uint32_t mbar, uint32_t parity) {
    uint32_t done;
    asm volatile("{\n\t.reg .pred p;\n\t"
                 "mbarrier.try_wait.parity.acquire.cta.shared::cta.b64 p, [%1], %2;\n\t"
                 "selp.b32 %0, 1, 0, p;\n\t}" : "=r"(done) : "r"(mbar), "r"(parity) : "memory");
    while (!done) {
        asm volatile("{\n\t.reg .pred p;\n\t"
                     "mbarrier.try_wait.parity.acquire.cta.shared::cta.b64 p, [%1], %2, 0x989680;\n\t"
                     "selp.b32 %0, 1, 0, p;\n\t}" : "=r"(done) : "r"(mbar), "r"(parity) : "memory");
    }
}

// Phase-2 inner: BASE = 8 (ig even) or 6 (ig odd), compile-time.
template <int BASE>
__device__ __forceinline__ void corr_accum(const ull* __restrict__ V, ull LpX, ull LpY,
                                           ull* __restrict__ aP, ull* __restrict__ aQ)
{
    #pragma unroll
    for (int dd = 0; dd < 6; dd++) {
        ull v0, v1;
        if ((dd & 1) == 0) {
            v0 = V[(BASE - dd) / 2];
            v1 = V[(BASE + 2 - dd) / 2];
        } else {
            const float2* a = (const float2*)&V[(BASE - 1 - dd) / 2];
            const float2* bq = (const float2*)&V[(BASE + 1 - dd) / 2];
            const float2* cq = (const float2*)&V[(BASE + 3 - dd) / 2];
            v0 = pack2(a->y, bq->x);
            v1 = pack2(bq->y, cq->x);
        }
        aP[dd] = fma2(LpX, v0, aP[dd]);
        aQ[dd] = fma2(LpY, v1, aQ[dd]);
    }
}

// One block per (b, h, half). 384 threads, 3 CTAs/SM.
__global__ __launch_bounds__(384, 3) void fused_kernel(
    const float* __restrict__ inL, const float* __restrict__ inR,
    const float* __restrict__ bg,  const float* __restrict__ bb,
    const float* __restrict__ bm,  const float* __restrict__ bv,
    const float* __restrict__ cw,  const float* __restrict__ cb,
    float* __restrict__ out)
{
    extern __shared__ char smraw[];
    ull*   sW   = (ull*)(smraw + OFF_SW);     // [80][32] splatted folded weights
    ull*   sB   = (ull*)(smraw + OFF_SB);     // [32]
    float* feat = (float*)(smraw + OFF_FEAT); // staging, later Ls|RA
    float* Ls   = feat;                       // [32][160] (scaled by 1/32)
    float* RA   = feat + 32*WH;               // [32][208]: RA[o][j] = featR[o][w0-48+j]
    const uint32_t smbase = s2u(smraw);
    const uint32_t mb0 = smbase + OFF_MBAR;

    const int tid  = threadIdx.x;
    const int bh   = blockIdx.x;
    const int half = blockIdx.y;
    const int h    = bh % HH, b = bh / HH;
    const long base_in = (long)b * CIN * HW + (long)h * WW + half * WH;
    const uint32_t txbytes = half ? (CHUNK * (640 + 832)) : (CHUNK * (640 + 640));

    // ---- Phase 0 ----
    if (tid == 0) { mbar_init(mb0, 1); mbar_init(mb0 + 8, 1); }
    __syncthreads();

    if (tid == 0) {
        #pragma unroll
        for (int k = 0; k < 2; k++) {
            uint32_t mbar = mb0 + k * 8;
            mbar_expect(mbar, txbytes);
            uint32_t dst = smbase + OFF_FEAT + k * BUFBYTES;
            const float* srcL = inL + base_in + (long)(k * CHUNK) * HW;
            const float* srcR = inR + base_in + (long)(k * CHUNK) * HW - (half ? 48 : 0);
            for (int cc = 0; cc < CHUNK; cc++) {
                bulk1d(dst + cc * 1472, srcL + (long)cc * HW, 640, mbar);
                if (half) bulk1d(dst + cc * 1472 + 640, srcR + (long)cc * HW, 832, mbar);
                else      bulk1d(dst + cc * 1472 + 832, srcR + (long)cc * HW, 640, mbar);
            }
        }
    }

    // zero halo pads in both staging buffers (half==0 only; persists across chunks)
    if (half == 0) {
        for (int idx = tid; idx < 2 * CHUNK * 48; idx += 384) {
            int s  = idx / (CHUNK * 48);
            int r  = idx % (CHUNK * 48);
            int cc = r / 48, j = r % 48;
            feat[s * BUFFLT + cc * SROW + 160 + j] = 0.f;
        }
    }

    for (int idx = tid; idx < CIN * COUT; idx += 384) {
        int c = idx >> 5, o = idx & 31;
        float sc = bg[c] * rsqrtf(bv[c] + 1e-5f);
        float wv = cw[o * CIN + c] * sc;
        sW[idx] = pack2(wv, wv);
    }
    if (tid < COUT) {
        float s = cb[tid];
        for (int c = 0; c < CIN; c++) {
            float sc = bg[c] * rsqrtf(bv[c] + 1e-5f);
            s += cw[tid * CIN + c] * (bb[c] - bm[c] * sc);
        }
        sB[tid] = pack2(s, s);
    }
    __syncthreads();

    // ---- Phase 1: preconv. Item = (og, g): og = outputs og*8..og*8+7;
    // g<40: L group wl0=4g; g>=40: R group j0=4(g-40). Staging addr = 4g uniform.
    const bool act = tid < 368;
    const int g  = tid % 92;
    const int og = act ? (tid / 92) : 0;

    ull accA[8], accB[8];
    #pragma unroll
    for (int oo = 0; oo < 8; oo++) { accA[oo] = sB[og * 8 + oo]; accB[oo] = accA[oo]; }

    for (int k = 0; k < NCHUNK; k++) {
        const int s = k & 1;
        mbar_wait(mb0 + s * 8, (k >> 1) & 1);
        if (act) {
            const float* bufD = feat + s * BUFFLT + 4 * g;
            #pragma unroll 2
            for (int cc = 0; cc < CHUNK; cc++) {
                float4 xv = *(const float4*)(bufD + cc * SROW);
                ull x01 = pack2(fmaxf(xv.x, 0.f), fmaxf(xv.y, 0.f));
                ull x23 = pack2(fmaxf(xv.z, 0.f), fmaxf(xv.w, 0.f));
                const ulonglong2* wr = (const ulonglong2*)&sW[(k * CHUNK + cc) * 32 + og * 8];
                #pragma unroll
                for (int j = 0; j < 4; j++) {
                    ulonglong2 W2 = wr[j];
                    accA[2*j]   = fma2(x01, W2.x, accA[2*j]);
                    accB[2*j]   = fma2(x23, W2.x, accB[2*j]);
                    accA[2*j+1] = fma2(x01, W2.y, accA[2*j+1]);
                    accB[2*j+1] = fma2(x23, W2.y, accB[2*j+1]);
                }
            }
        }
        __syncthreads();   // buffer s fully consumed
        if (tid == 0 && k + 2 < NCHUNK) {
            int kn = k + 2;
            uint32_t mbar = mb0 + s * 8;
            mbar_expect(mbar, txbytes);
            uint32_t dst = smbase + OFF_FEAT + s * BUFBYTES;
            const float* srcL = inL + base_in + (long)(kn * CHUNK) * HW;
            const float* srcR = inR + base_in + (long)(kn * CHUNK) * HW - (half ? 48 : 0);
            for (int cc = 0; cc < CHUNK; cc++) {
                bulk1d(dst + cc * 1472, srcL + (long)cc * HW, 640, mbar);
                if (half) bulk1d(dst + cc * 1472 + 640, srcR + (long)cc * HW, 832, mbar);
                else      bulk1d(dst + cc * 1472 + 832, srcR + (long)cc * HW, 640, mbar);
            }
        }
    }

    // store features (overlay onto staging region; safe after final sync)
    if (act) {
        if (g < 40) {
            const ull inv2 = pack2(0.03125f, 0.03125f);   // fold 1/32 into L
            #pragma unroll
            for (int oo = 0; oo < 8; oo++) {
                int o = og * 8 + oo;
                ulonglong2 v; v.x = mul2(accA[oo], inv2); v.y = mul2(accB[oo], inv2);
                *(ulonglong2*)&Ls[o * WH + 4 * g] = v;
            }
        } else {
            const int j0 = 4 * (g - 40);
            const bool zero = (half == 0) && (j0 < 48);   // w<0 features are 0
            #pragma unroll
            for (int oo = 0; oo < 8; oo++) {
                int o = og * 8 + oo;
                ulonglong2 v;
                v.x = zero ? 0ULL : accA[oo];
                v.y = zero ? 0ULL : accB[oo];
                *(ulonglong2*)&RA[o * RW + j0] = v;
            }
        }
    }
    __syncthreads();

    // ---- Phase 2: correlation. Tile = 2 pairs (4 w) x 6 disparities; 320 tiles.
    if (tid < 320) {
        const int wq = tid % 40, ig = tid / 40;
        const int W0 = 4 * wq;          // local w
        const int i0 = 6 * ig;
        const int rb = W0 + ((43 - i0) & ~3);   // 16B-aligned V window base

        ull aP[6], aQ[6];
        #pragma unroll
        for (int d = 0; d < 6; d++) { aP[d] = 0ULL; aQ[d] = 0ULL; }

        #pragma unroll 2
        for (int c = 0; c < 32; c++) {
            ulonglong2 Lp = *(const ulonglong2*)&Ls[c * WH + W0];
            const float* rr = &RA[c * RW + rb];
            ull V[6];
            #pragma unroll
            for (int m = 0; m < 3; m++) {
                ulonglong2 t2 = *(const ulonglong2*)&rr[4 * m];   // LDS.128
                V[2*m] = t2.x; V[2*m+1] = t2.y;
            }
            if (ig & 1) corr_accum<6>(V, Lp.x, Lp.y, aP, aQ);
            else        corr_accum<8>(V, Lp.x, Lp.y, aP, aQ);
        }

        float* outp = out + ((long)(b * DD + i0) * HH + h) * WW + half * WH + W0;
        #pragma unroll
        for (int dd = 0; dd < 6; dd++) {
            float2 p = *(float2*)&aP[dd];
            float2 q = *(float2*)&aQ[dd];
            float4 v; v.x = p.x; v.y = p.y; v.z = q.x; v.w = q.y;
            *(float4*)&outp[(long)dd * HW] = v;
        }
    }
}

// ---------------------------------------------------------------------------
extern "C" void kernel_launch(void* const* d_in, const int* in_sizes, int n_in,
                              void* d_out, int out_size)
{
    const float* fL = (const float*)d_in[0];
    const float* fR = (const float*)d_in[1];
    const float* bg = (const float*)d_in[2];
    const float* bb = (const float*)d_in[3];
    const float* bm = (const float*)d_in[4];
    const float* bv = (const float*)d_in[5];
    const float* cw = (const float*)d_in[6];
    const float* cb = (const float*)d_in[7];
    float* out = (float*)d_out;

    cudaFuncSetAttribute(fused_kernel, cudaFuncAttributeMaxDynamicSharedMemorySize, SMEM_TOTAL);
    dim3 grid(BATCH * HH, 2);
    fused_kernel<<<grid, 384, SMEM_TOTAL>>>(fL, fR, bg, bb, bm, bv, cw, cb, out);
}

// round 12
// speedup vs baseline: 1.1257x; 1.1257x over previous
#include <cuda_runtime.h>
#include <cstdint>

#define CIN   80
#define COUT  32
#define BATCH 8
#define HH    160
#define WW    320
#define DD    48
#define HW    (HH*WW)      // 51200
#define RSTR  376          // padded R row stride: 48 zero + 320 + 8 (16B-mult)
#define CHUNK 16
#define NCHUNK 5
#define BUFBYTES (2*CHUNK*WW*4)   // 40960 B per stage buffer

#define OFF_SW   0
#define OFF_SB   20480
#define OFF_MBAR 20736
#define OFF_FEAT 20800
#define SMEM_TOTAL (20800 + (32*WW + 32*RSTR)*4)   // 109888 -> 2 CTAs/SM

typedef unsigned long long ull;

__device__ __forceinline__ ull fma2(ull a, ull b, ull c) {
    ull d;
    asm("fma.rn.f32x2 %0, %1, %2, %3;" : "=l"(d) : "l"(a), "l"(b), "l"(c));
    return d;
}
__device__ __forceinline__ ull mul2(ull a, ull b) {
    ull d;
    asm("mul.rn.f32x2 %0, %1, %2;" : "=l"(d) : "l"(a), "l"(b));
    return d;
}
__device__ __forceinline__ ull pack2(float lo, float hi) {
    ull d;
    asm("mov.b64 %0, {%1, %2};" : "=l"(d) : "f"(lo), "f"(hi));
    return d;
}
__device__ __forceinline__ uint32_t s2u(const void* p) {
    uint32_t a;
    asm("{ .reg .u64 t; cvta.to.shared.u64 t, %1; cvt.u32.u64 %0, t; }" : "=r"(a) : "l"(p));
    return a;
}
__device__ __forceinline__ void bulk1d(uint32_t dst, const void* src, uint32_t bytes, uint32_t mbar) {
    asm volatile("cp.async.bulk.shared::cluster.global.mbarrier::complete_tx::bytes [%0], [%1], %2, [%3];"
                 :: "r"(dst), "l"(src), "r"(bytes), "r"(mbar) : "memory");
}
__device__ __forceinline__ void mbar_init(uint32_t mbar, uint32_t cnt) {
    asm volatile("mbarrier.init.shared.b64 [%0], %1;" :: "r"(mbar), "r"(cnt) : "memory");
}
__device__ __forceinline__ void mbar_expect(uint32_t mbar, uint32_t tx) {
    asm volatile("mbarrier.arrive.expect_tx.shared.b64 _, [%0], %1;" :: "r"(mbar), "r"(tx) : "memory");
}
__device__ __forceinline__ void mbar_wait(uint32_t mbar, uint32_t parity) {
    uint32_t done;
    asm volatile("{\n\t.reg .pred p;\n\t"
                 "mbarrier.try_wait.parity.acquire.cta.shared::cta.b64 p, [%1], %2;\n\t"
                 "selp.b32 %0, 1, 0, p;\n\t}" : "=r"(done) : "r"(mbar), "r"(parity) : "memory");
    while (!done) {
        asm volatile("{\n\t.reg .pred p;\n\t"
                     "mbarrier.try_wait.parity.acquire.cta.shared::cta.b64 p, [%1], %2, 0x989680;\n\t"
                     "selp.b32 %0, 1, 0, p;\n\t}" : "=r"(done) : "r"(mbar), "r"(parity) : "memory");
    }
}

// One block per (b,h) row. 320 threads, 2 CTAs/SM.
__global__ __launch_bounds__(320, 2) void fused_kernel(
    const float* __restrict__ inL, const float* __restrict__ inR,
    const float* __restrict__ bg,  const float* __restrict__ bb,
    const float* __restrict__ bm,  const float* __restrict__ bv,
    const float* __restrict__ cw,  const float* __restrict__ cb,
    float* __restrict__ out)
{
    extern __shared__ char smraw[];
    ull*   sW   = (ull*)(smraw + OFF_SW);     // [80][32] splatted folded weights
    ull*   sB   = (ull*)(smraw + OFF_SB);     // [32]
    float* feat = (float*)(smraw + OFF_FEAT); // staging, later Ls|RA
    float* Ls   = feat;                       // [32][320] (scaled by 1/32)
    float* RA   = feat + 32*WW;               // [32][376]
    const uint32_t smbase = s2u(smraw);
    const uint32_t mb0 = smbase + OFF_MBAR;

    const int tid = threadIdx.x;
    const int bh  = blockIdx.x;
    const int h   = bh % HH, b = bh / HH;
    const long base_in = (long)b * CIN * HW + (long)h * WW;

    // ---- Phase 0 ----
    if (tid == 0) { mbar_init(mb0, 1); mbar_init(mb0 + 8, 1); }
    __syncthreads();

    if (tid == 0) {
        #pragma unroll
        for (int k = 0; k < 2; k++) {
            uint32_t mbar = mb0 + k * 8;
            mbar_expect(mbar, BUFBYTES);
            uint32_t dst = smbase + OFF_FEAT + k * BUFBYTES;
            const float* srcL = inL + base_in + (long)(k * CHUNK) * HW;
            const float* srcR = inR + base_in + (long)(k * CHUNK) * HW;
            for (int cc = 0; cc < CHUNK; cc++) {
                bulk1d(dst + cc * 1280,                srcL + (long)cc * HW, 1280, mbar);
                bulk1d(dst + CHUNK * 1280 + cc * 1280, srcR + (long)cc * HW, 1280, mbar);
            }
        }
    }

    for (int idx = tid; idx < CIN * COUT; idx += 320) {
        int c = idx >> 5, o = idx & 31;
        float sc = bg[c] * rsqrtf(bv[c] + 1e-5f);
        float wv = cw[o * CIN + c] * sc;
        sW[idx] = pack2(wv, wv);
    }
    if (tid < COUT) {
        float s = cb[tid];
        for (int c = 0; c < CIN; c++) {
            float sc = bg[c] * rsqrtf(bv[c] + 1e-5f);
            s += cw[tid * CIN + c] * (bb[c] - bm[c] * sc);
        }
        sB[tid] = pack2(s, s);
    }
    __syncthreads();

    // ---- Phase 1: preconv. Thread = (u, img, og): quads at cols 4u and 4u+160
    // of image img, outputs og*8..og*8+7. 2 data LDS.128 + 4 weight LDS.128
    // per channel for 32 FFMA2.
    const int u   = tid % 40;
    const int img = (tid / 40) & 1;
    const int og  = tid / 80;            // 0..3

    // acc[quad][pair][out]: A = col 4u, B = col 4u+160; 2 pairs per quad
    ull aA0[8], aA1[8], aB0[8], aB1[8];
    #pragma unroll
    for (int oo = 0; oo < 8; oo++) {
        ull bias = sB[og * 8 + oo];
        aA0[oo] = bias; aA1[oo] = bias; aB0[oo] = bias; aB1[oo] = bias;
    }

    for (int k = 0; k < NCHUNK; k++) {
        const int s = k & 1;
        mbar_wait(mb0 + s * 8, (k >> 1) & 1);
        const float* bufD = feat + s * (BUFBYTES / 4) + img * (CHUNK * WW) + 4 * u;

        #pragma unroll 2
        for (int cc = 0; cc < CHUNK; cc++) {
            float4 a0 = *(const float4*)(bufD + cc * WW);          // quad A
            float4 a1 = *(const float4*)(bufD + cc * WW + 160);    // quad B
            ull xA0 = pack2(fmaxf(a0.x, 0.f), fmaxf(a0.y, 0.f));
            ull xA1 = pack2(fmaxf(a0.z, 0.f), fmaxf(a0.w, 0.f));
            ull xB0 = pack2(fmaxf(a1.x, 0.f), fmaxf(a1.y, 0.f));
            ull xB1 = pack2(fmaxf(a1.z, 0.f), fmaxf(a1.w, 0.f));
            const ulonglong2* wr = (const ulonglong2*)&sW[(k * CHUNK + cc) * 32 + og * 8];
            #pragma unroll
            for (int j = 0; j < 4; j++) {
                ulonglong2 W2 = wr[j];     // outs 2j, 2j+1 (splatted), LDS.128
                aA0[2*j]   = fma2(xA0, W2.x, aA0[2*j]);
                aA1[2*j]   = fma2(xA1, W2.x, aA1[2*j]);
                aB0[2*j]   = fma2(xB0, W2.x, aB0[2*j]);
                aB1[2*j]   = fma2(xB1, W2.x, aB1[2*j]);
                aA0[2*j+1] = fma2(xA0, W2.y, aA0[2*j+1]);
                aA1[2*j+1] = fma2(xA1, W2.y, aA1[2*j+1]);
                aB0[2*j+1] = fma2(xB0, W2.y, aB0[2*j+1]);
                aB1[2*j+1] = fma2(xB1, W2.y, aB1[2*j+1]);
            }
        }
        __syncthreads();   // buffer s fully consumed
        if (tid == 0 && k + 2 < NCHUNK) {
            int kn = k + 2;
            uint32_t mbar = mb0 + s * 8;
            mbar_expect(mbar, BUFBYTES);
            uint32_t dst = smbase + OFF_FEAT + s * BUFBYTES;
            const float* srcL = inL + base_in + (long)(kn * CHUNK) * HW;
            const float* srcR = inR + base_in + (long)(kn * CHUNK) * HW;
            for (int cc = 0; cc < CHUNK; cc++) {
                bulk1d(dst + cc * 1280,                srcL + (long)cc * HW, 1280, mbar);
                bulk1d(dst + CHUNK * 1280 + cc * 1280, srcR + (long)cc * HW, 1280, mbar);
            }
        }
    }

    // zero RA pads: cols [0,48) and [368,376)
    for (int idx = tid; idx < 32 * 56; idx += 320) {
        int o = idx / 56, j = idx % 56;
        RA[o * RSTR + (j < 48 ? j : 320 + j)] = 0.f;
    }
    // store features (fold 1/32 into L)
    if (img == 0) {
        const ull inv2 = pack2(0.03125f, 0.03125f);
        #pragma unroll
        for (int oo = 0; oo < 8; oo++) {
            int o = og * 8 + oo;
            ulonglong2 vA; vA.x = mul2(aA0[oo], inv2); vA.y = mul2(aA1[oo], inv2);
            ulonglong2 vB; vB.x = mul2(aB0[oo], inv2); vB.y = mul2(aB1[oo], inv2);
            *(ulonglong2*)&Ls[o * WW + 4 * u]       = vA;
            *(ulonglong2*)&Ls[o * WW + 4 * u + 160] = vB;
        }
    } else {
        #pragma unroll
        for (int oo = 0; oo < 8; oo++) {
            int o = og * 8 + oo;
            ulonglong2 vA; vA.x = aA0[oo]; vA.y = aA1[oo];
            ulonglong2 vB; vB.x = aB0[oo]; vB.y = aB1[oo];
            *(ulonglong2*)&RA[o * RSTR + 4 * u + 48]  = vA;
            *(ulonglong2*)&RA[o * RSTR + 4 * u + 208] = vB;
        }
    }
    __syncthreads();

    // ---- Phase 2: correlation (R7-proven). Thread = (wq, ig): 2 pairs x 12 disp.
    const int wq = tid % 80, ig = tid / 80;
    const int W0 = 4 * wq;
    const int i0 = 12 * ig;

    ull aP[12], aQ[12];
    #pragma unroll
    for (int d = 0; d < 12; d++) { aP[d] = 0ULL; aQ[d] = 0ULL; }

    #pragma unroll 2
    for (int c = 0; c < 32; c++) {
        ulonglong2 Lp = *(const ulonglong2*)&Ls[c * WW + W0];
        const float* rr = &RA[c * RSTR + W0 + 36 - i0];
        ull V[8];
        #pragma unroll
        for (int m = 0; m < 4; m++) {
            ulonglong2 t = *(const ulonglong2*)&rr[4 * m];
            V[2*m] = t.x; V[2*m+1] = t.y;
        }
        #pragma unroll
        for (int dd = 0; dd < 12; dd++) {
            ull v0, v1;
            if ((dd & 1) == 0) {
                v0 = V[(12 - dd) / 2];
                v1 = V[(14 - dd) / 2];
            } else {
                const float2* f11 = (const float2*)&V[(11 - dd) / 2];
                const float2* f13 = (const float2*)&V[(13 - dd) / 2];
                const float2* f15 = (const float2*)&V[(15 - dd) / 2];
                v0 = pack2(f11->y, f13->x);
                v1 = pack2(f13->y, f15->x);
            }
            aP[dd] = fma2(Lp.x, v0, aP[dd]);
            aQ[dd] = fma2(Lp.y, v1, aQ[dd]);
        }
    }

    float* outp = out + ((long)b * DD * HH + h) * WW;
    #pragma unroll
    for (int dd = 0; dd < 12; dd++) {
        float2 p = *(float2*)&aP[dd];
        float2 q = *(float2*)&aQ[dd];
        float4 v; v.x = p.x; v.y = p.y; v.z = q.x; v.w = q.y;
        *(float4*)&outp[(long)(i0 + dd) * HW + W0] = v;
    }
}

// ---------------------------------------------------------------------------
extern "C" void kernel_launch(void* const* d_in, const int* in_sizes, int n_in,
                              void* d_out, int out_size)
{
    const float* fL = (const float*)d_in[0];
    const float* fR = (const float*)d_in[1];
    const float* bg = (const float*)d_in[2];
    const float* bb = (const float*)d_in[3];
    const float* bm = (const float*)d_in[4];
    const float* bv = (const float*)d_in[5];
    const float* cw = (const float*)d_in[6];
    const float* cb = (const float*)d_in[7];
    float* out = (float*)d_out;

    cudaFuncSetAttribute(fused_kernel, cudaFuncAttributeMaxDynamicSharedMemorySize, SMEM_TOTAL);
    fused_kernel<<<BATCH*HH, 320, SMEM_TOTAL>>>(fL, fR, bg, bb, bm, bv, cw, cb, out);
}